// round 3
// baseline (speedup 1.0000x reference)
#include <cuda_runtime.h>
#include <math.h>

#define N_ATOMS 8192
#define D_DIM   128
#define K_MAX   4224
#define SPLIT_A 8
#define TWO_PI  6.28318530717958647692f

typedef unsigned long long u64;

// ---------------- static device scratch ----------------
__device__ float2 g_csf[(size_t)K_MAX * N_ATOMS];   // [K][N] {cos,sin} fwd
__device__ float2 g_csi[(size_t)N_ATOMS * K_MAX];   // [N][K] {cos,sin} inv
__device__ float g_pKr[SPLIT_A][(size_t)K_MAX * D_DIM];
__device__ float g_pKi[SPLIT_A][(size_t)K_MAX * D_DIM];
__device__ float g_pVr[SPLIT_A][(size_t)K_MAX * D_DIM];
__device__ float g_pVi[SPLIT_A][(size_t)K_MAX * D_DIM];
__device__ float g_vpr[K_MAX * D_DIM];
__device__ float g_vpi[K_MAX * D_DIM];
__device__ float g_akp[K_MAX * D_DIM];
__device__ float g_qabs[(size_t)N_ATOMS * D_DIM];
__device__ float g_aw[(size_t)N_ATOMS * K_MAX];
__device__ u64   g_pD[2][(size_t)N_ATOMS * 64];

// ---------------- f32x2 helpers ----------------
__device__ __forceinline__ u64 pk2(float lo, float hi) {
    u64 r; asm("mov.b64 %0,{%1,%2};" : "=l"(r) : "f"(lo), "f"(hi)); return r;
}
__device__ __forceinline__ u64 dup2(float x) { return pk2(x, x); }
__device__ __forceinline__ void fma2(u64& d, u64 a, u64 b) {
    asm("fma.rn.f32x2 %0,%1,%2,%0;" : "+l"(d) : "l"(a), "l"(b));
}
__device__ __forceinline__ float2 up2(u64 v) {
    float2 f; asm("mov.b64 {%0,%1},%2;" : "=f"(f.x), "=f"(f.y) : "l"(v)); return f;
}

// ---------------- plane-wave table helper ----------------
__device__ __forceinline__ void build_tables_one(
    float rx, float ry, float rz,
    float* exr, float* exi, float* eyr, float* eyi,
    float* ezr, float* ezi, int pitch)
{
    #pragma unroll
    for (int j = 0; j <= 12; j++) {
        float s, c;
        sincosf(TWO_PI * rx * (float)j, &s, &c);
        exr[j * pitch] = c; exi[j * pitch] = s;
    }
    #pragma unroll
    for (int j = 0; j <= 12; j++) {
        float s, c;
        sincosf(TWO_PI * ry * (float)j, &s, &c);
        eyr[(12 + j) * pitch] = c; eyi[(12 + j) * pitch] = s;
        eyr[(12 - j) * pitch] = c; eyi[(12 - j) * pitch] = -s;
    }
    #pragma unroll
    for (int j = 0; j <= 12; j++) {
        float s, c;
        sincosf(TWO_PI * rz * (float)j, &s, &c);
        ezr[(12 + j) * pitch] = c; ezi[(12 + j) * pitch] = s;
        ezr[(12 - j) * pitch] = c; ezi[(12 - j) * pitch] = -s;
    }
}

// ---------------- kernel 1a: forward E matrix [K][N] ----------------
__global__ void __launch_bounds__(256) k_build_fwd(
    const float* __restrict__ pos, const float* __restrict__ cell,
    const int* __restrict__ kfwd, int K)
{
    __shared__ float exr[13][32], exi[13][32];
    __shared__ float eyr[25][32], eyi[25][32];
    __shared__ float ezr[25][32], ezi[25][32];

    const int tx = threadIdx.x, ty = threadIdx.y;
    const int n0 = blockIdx.x * 32;

    if (ty == 0) {
        int n = n0 + tx;
        float bx = cell[0], by = cell[4], bz = cell[8];
        build_tables_one(pos[n*3+0]/bx, pos[n*3+1]/by, pos[n*3+2]/bz,
                         &exr[0][tx], &exi[0][tx], &eyr[0][tx], &eyi[0][tx],
                         &ezr[0][tx], &ezi[0][tx], 32);
    }
    __syncthreads();

    for (int k = ty; k < K; k += 8) {
        int a = kfwd[3*k+0], b = kfwd[3*k+1] + 12, c = kfwd[3*k+2] + 12;
        float xr = exr[a][tx], xi = exi[a][tx];
        float yr = eyr[b][tx], yi = eyi[b][tx];
        float zr = ezr[c][tx], zi = ezi[c][tx];
        float pr = xr*yr - xi*yi, pi = xr*yi + xi*yr;
        g_csf[(size_t)k * N_ATOMS + n0 + tx] =
            make_float2(pr*zr - pi*zi, pr*zi + pi*zr);
    }
}

// ---------------- kernel 1b: inverse E matrix [N][K] ----------------
__global__ void __launch_bounds__(256) k_build_inv(
    const float* __restrict__ pos, const float* __restrict__ cell,
    const int* __restrict__ kinv, int K)
{
    __shared__ float exr[13][9], exi[13][9];
    __shared__ float eyr[25][9], eyi[25][9];
    __shared__ float ezr[25][9], ezi[25][9];

    const int tx = threadIdx.x, ty = threadIdx.y;
    const int tid = tx + 32 * ty;
    const int n0 = blockIdx.x * 8;

    if (tid < 8) {
        int n = n0 + tid;
        float bx = cell[0], by = cell[4], bz = cell[8];
        build_tables_one(pos[n*3+0]/bx, pos[n*3+1]/by, pos[n*3+2]/bz,
                         &exr[0][tid], &exi[0][tid], &eyr[0][tid], &eyi[0][tid],
                         &ezr[0][tid], &ezi[0][tid], 9);
    }
    __syncthreads();

    for (int k = tx; k < K; k += 32) {
        int a = kinv[3*k+0], b = kinv[3*k+1] + 12, c = kinv[3*k+2] + 12;
        float xr = exr[a][ty], xi = exi[a][ty];
        float yr = eyr[b][ty], yi = eyi[b][ty];
        float zr = ezr[c][ty], zi = ezi[c][ty];
        float pr = xr*yr - xi*yi, pi = xr*yi + xi*yr;
        g_csi[(size_t)(n0 + ty) * K + k] =
            make_float2(pr*zr - pi*zi, pr*zi + pi*zr);
    }
}

// ---------------- kernel 1c: |q| ----------------
__global__ void k_absq(const float* __restrict__ q)
{
    int i = blockIdx.x * 256 + threadIdx.x;
    g_qabs[i] = fabsf(q[i]);
}

// ---------------- kernel 2: phase A split-N GEMM ----------------
// tile 32k x 128d; thread: 4 k-rows (ty*4+j) x 2 d-pairs (d = 2*tx + 64*p).
// Inner loop is pure LDS.64 + FFMA2 (cos/sin pre-duplicated in smem).
__global__ void __launch_bounds__(256, 2) k_phaseA(
    const float* __restrict__ kv, const float* __restrict__ vv, int K)
{
    __shared__ u64  s_cc[32][32];   // [kl][n] {c,c}
    __shared__ u64  s_ss[32][32];   // [kl][n] {s,s}
    __shared__ float s_k[32][128];  // [n][d]
    __shared__ float s_v[32][128];

    const int t  = threadIdx.x;
    const int tx = t & 31;
    const int ty = t >> 5;
    const int k0 = blockIdx.x * 32;
    const int nb0 = blockIdx.y * (N_ATOMS / SPLIT_A);
    const int nb_end = nb0 + (N_ATOMS / SPLIT_A);

    u64 aKr[4][2], aKi[4][2], aVr[4][2], aVi[4][2];
    #pragma unroll
    for (int j = 0; j < 4; j++)
        #pragma unroll
        for (int p = 0; p < 2; p++) {
            aKr[j][p] = 0ull; aKi[j][p] = 0ull;
            aVr[j][p] = 0ull; aVi[j][p] = 0ull;
        }

    for (int nb = nb0; nb < nb_end; nb += 32) {
        __syncthreads();
        #pragma unroll
        for (int j = 0; j < 4; j++) {
            int kl = ty + 8 * j;
            float2 cs = g_csf[(size_t)(k0 + kl) * N_ATOMS + nb + tx];
            s_cc[kl][tx] = dup2(cs.x);
            s_ss[kl][tx] = dup2(cs.y);
        }
        #pragma unroll
        for (int j = 0; j < 4; j++) {
            int row = ty + 8 * j;
            *(float4*)&s_k[row][tx*4] = *(const float4*)&kv[(size_t)(nb+row)*128 + tx*4];
            *(float4*)&s_v[row][tx*4] = *(const float4*)&vv[(size_t)(nb+row)*128 + tx*4];
        }
        __syncthreads();

        #pragma unroll
        for (int nn = 0; nn < 32; nn++) {
            u64 cc[4], ss[4];
            #pragma unroll
            for (int j = 0; j < 4; j++) {
                cc[j] = s_cc[ty*4 + j][nn];
                ss[j] = s_ss[ty*4 + j][nn];
            }
            #pragma unroll
            for (int p = 0; p < 2; p++) {
                int d = 2 * tx + 64 * p;
                u64 kd = *(const u64*)&s_k[nn][d];
                u64 vd = *(const u64*)&s_v[nn][d];
                #pragma unroll
                for (int j = 0; j < 4; j++) {
                    fma2(aKr[j][p], cc[j], kd);
                    fma2(aKi[j][p], ss[j], kd);
                    fma2(aVr[j][p], cc[j], vd);
                    fma2(aVi[j][p], ss[j], vd);
                }
            }
        }
    }

    const int sp = blockIdx.y;
    #pragma unroll
    for (int j = 0; j < 4; j++) {
        int k = k0 + ty*4 + j;
        if (k < K) {
            #pragma unroll
            for (int p = 0; p < 2; p++) {
                size_t o = (size_t)k * 128 + 2 * tx + 64 * p;
                *(u64*)&g_pKr[sp][o] = aKr[j][p];
                *(u64*)&g_pKi[sp][o] = aKi[j][p];
                *(u64*)&g_pVr[sp][o] = aVr[j][p];
                *(u64*)&g_pVi[sp][o] = aVi[j][p];
            }
        }
    }
}

// ---------------- kernel 3: reduce splits + |k_pot| ----------------
__global__ void k_reduceA(int K)
{
    int i = blockIdx.x * 256 + threadIdx.x;
    if (i >= K * 128) return;
    float kr = 0.f, ki = 0.f, vr = 0.f, vi = 0.f;
    #pragma unroll
    for (int s = 0; s < SPLIT_A; s++) {
        kr += g_pKr[s][i]; ki += g_pKi[s][i];
        vr += g_pVr[s][i]; vi += g_pVi[s][i];
    }
    g_vpr[i] = vr; g_vpi[i] = vi;
    g_akp[i] = sqrtf(kr*kr + ki*ki);
}

// ---------------- kernel 4: aw = |q| @ |k_pot|^T ----------------
// tile 128n x 64k; |q| pre-duplicated in smem; acc packed over k-pairs.
__global__ void __launch_bounds__(256) k_phaseB(int K)
{
    __shared__ u64  s_a[16][128];   // [d][n] {q,q}
    __shared__ float s_b[16][68];   // [d][k]

    const int t  = threadIdx.x;
    const int tx = t & 15;          // k cols tx*4..+3
    const int ty = t >> 4;          // n rows ty*8..+7
    const int kb = blockIdx.x * 64;
    const int nb = blockIdx.y * 128;

    u64 ac[8][2];
    #pragma unroll
    for (int i = 0; i < 8; i++) { ac[i][0] = 0ull; ac[i][1] = 0ull; }

    for (int d0 = 0; d0 < 128; d0 += 16) {
        __syncthreads();
        #pragma unroll
        for (int i = 0; i < 8; i++) {
            int r = ty + 16 * i;
            s_a[tx][r] = dup2(g_qabs[(size_t)(nb + r) * 128 + d0 + tx]);
        }
        #pragma unroll
        for (int i = 0; i < 4; i++) {
            int r = ty + 16 * i;
            s_b[tx][r] = (kb + r < K) ? g_akp[(kb + r) * 128 + d0 + tx] : 0.f;
        }
        __syncthreads();
        #pragma unroll
        for (int dd = 0; dd < 16; dd++) {
            ulonglong2 b = *(const ulonglong2*)&s_b[dd][tx * 4];
            #pragma unroll
            for (int i = 0; i < 8; i++) {
                u64 A = s_a[dd][ty * 8 + i];
                fma2(ac[i][0], A, b.x);
                fma2(ac[i][1], A, b.y);
            }
        }
    }
    #pragma unroll
    for (int i = 0; i < 8; i++) {
        int n = nb + ty * 8 + i;
        size_t base = (size_t)n * K + kb + tx * 4;
        float2 lo = up2(ac[i][0]), hi = up2(ac[i][1]);
        float vals[4] = {lo.x, lo.y, hi.x, hi.y};
        #pragma unroll
        for (int j = 0; j < 4; j++)
            if (kb + tx * 4 + j < K) g_aw[base + j] = vals[j];
    }
}

// ---------------- kernel 5: row softmax in place ----------------
__global__ void __launch_bounds__(256) k_softmax(int K)
{
    __shared__ float buf[K_MAX];
    __shared__ float red[8];
    const int n = blockIdx.x;
    const int t = threadIdx.x;
    float* row = g_aw + (size_t)n * K;

    float mx = -1e30f;
    for (int i = t; i < K; i += 256) { float v = row[i]; buf[i] = v; mx = fmaxf(mx, v); }
    #pragma unroll
    for (int o = 16; o; o >>= 1) mx = fmaxf(mx, __shfl_xor_sync(0xffffffffu, mx, o));
    if ((t & 31) == 0) red[t >> 5] = mx;
    __syncthreads();
    float gmax = red[0];
    #pragma unroll
    for (int j = 1; j < 8; j++) gmax = fmaxf(gmax, red[j]);
    __syncthreads();

    float s = 0.f;
    for (int i = t; i < K; i += 256) { float e = expf(buf[i] - gmax); buf[i] = e; s += e; }
    #pragma unroll
    for (int o = 16; o; o >>= 1) s += __shfl_xor_sync(0xffffffffu, s, o);
    if ((t & 31) == 0) red[t >> 5] = s;
    __syncthreads();
    float gsum = 0.f;
    #pragma unroll
    for (int j = 0; j < 8; j++) gsum += red[j];
    float inv = 1.f / gsum;
    for (int i = t; i < K; i += 256) row[i] = buf[i] * inv;
}

// ---------------- kernel 6: phase D (w pre-duplicated, split-K=2) ----------------
// tile 32n x 128d, k-tile 16; thread: 2 rows (ty*2+j) x 4 d-pairs (d=2*tx+32*p)
__global__ void __launch_bounds__(256) k_phaseD(int K)
{
    __shared__ u64  s_wr[32][16];    // [row][kk] {sm*ci, sm*ci}
    __shared__ u64  s_wi[32][16];
    __shared__ float s_vr[16][128];  // [kk][d]
    __shared__ float s_vi[16][128];

    const int t  = threadIdx.x;
    const int tx = t & 15;
    const int ty = t >> 4;
    const int n0 = blockIdx.x * 32;
    const int z  = blockIdx.y;

    const int ksteps = (K + 15) / 16;
    const int half = (ksteps + 1) / 2;
    const int ks_lo = z ? half : 0;
    const int ks_hi = z ? ksteps : half;

    u64 acc[2][4];
    #pragma unroll
    for (int j = 0; j < 2; j++)
        #pragma unroll
        for (int p = 0; p < 4; p++) acc[j][p] = 0ull;

    for (int ks = ks_lo; ks < ks_hi; ks++) {
        const int k0 = ks * 16;
        __syncthreads();
        // w fill: 32 rows x 16 kk
        #pragma unroll
        for (int j = 0; j < 2; j++) {
            int e = t + 256 * j;
            int row = e >> 4, kk = e & 15;
            float wr = 0.f, wi = 0.f;
            if (k0 + kk < K) {
                size_t gi = (size_t)(n0 + row) * K + k0 + kk;
                float sm = g_aw[gi];
                float2 cs = g_csi[gi];
                wr = sm * cs.x;
                wi = sm * cs.y;
            }
            s_wr[row][kk] = dup2(wr);
            s_wi[row][kk] = dup2(wi);
        }
        // v fill: 16 kk x 128 d
        #pragma unroll
        for (int j = 0; j < 2; j++) {
            int lin = t + 256 * j;
            int kk = lin >> 5, c4 = lin & 31;
            float4 a = make_float4(0.f, 0.f, 0.f, 0.f);
            float4 b = make_float4(0.f, 0.f, 0.f, 0.f);
            if (k0 + kk < K) {
                a = *(const float4*)&g_vpr[(k0 + kk) * 128 + c4 * 4];
                b = *(const float4*)&g_vpi[(k0 + kk) * 128 + c4 * 4];
            }
            *(float4*)&s_vr[kk][c4 * 4] = a;
            *(float4*)&s_vi[kk][c4 * 4] = b;
        }
        __syncthreads();

        #pragma unroll
        for (int kk = 0; kk < 16; kk++) {
            u64 wr0 = s_wr[ty*2 + 0][kk], wi0 = s_wi[ty*2 + 0][kk];
            u64 wr1 = s_wr[ty*2 + 1][kk], wi1 = s_wi[ty*2 + 1][kk];
            #pragma unroll
            for (int p = 0; p < 4; p++) {
                int d = 2 * tx + 32 * p;
                u64 vr = *(const u64*)&s_vr[kk][d];
                u64 vi = *(const u64*)&s_vi[kk][d];
                fma2(acc[0][p], wr0, vr); fma2(acc[0][p], wi0, vi);
                fma2(acc[1][p], wr1, vr); fma2(acc[1][p], wi1, vi);
            }
        }
    }

    #pragma unroll
    for (int j = 0; j < 2; j++) {
        int row = n0 + ty * 2 + j;
        #pragma unroll
        for (int p = 0; p < 4; p++)
            g_pD[z][(size_t)row * 64 + tx + 16 * p] = acc[j][p];
    }
}

// ---------------- kernel 7: phase D reduce ----------------
__global__ void k_reduceD(float* __restrict__ out)
{
    int i = blockIdx.x * 256 + threadIdx.x;
    float2 a = up2(g_pD[0][i]);
    float2 b = up2(g_pD[1][i]);
    ((float2*)out)[i] = make_float2(a.x + b.x, a.y + b.y);
}

// ---------------- launch ----------------
extern "C" void kernel_launch(void* const* d_in, const int* in_sizes, int n_in,
                              void* d_out, int out_size)
{
    const float* q    = (const float*)d_in[0];
    const float* kvec = (const float*)d_in[1];
    const float* vvec = (const float*)d_in[2];
    const float* pos  = (const float*)d_in[3];
    const float* cell = (const float*)d_in[4];
    const int*   kfwd = (const int*)d_in[6];
    const int*   kinv = (const int*)d_in[7];
    const int K = in_sizes[6] / 3;

    dim3 b(32, 8);
    k_build_fwd<<<N_ATOMS / 32, b>>>(pos, cell, kfwd, K);
    k_build_inv<<<N_ATOMS / 8, b>>>(pos, cell, kinv, K);
    k_absq<<<(N_ATOMS * D_DIM) / 256, 256>>>(q);

    dim3 gA((K + 31) / 32, SPLIT_A);
    k_phaseA<<<gA, 256>>>(kvec, vvec, K);
    k_reduceA<<<(K * D_DIM + 255) / 256, 256>>>(K);

    dim3 gB((K + 63) / 64, N_ATOMS / 128);
    k_phaseB<<<gB, 256>>>(K);
    k_softmax<<<N_ATOMS, 256>>>(K);

    dim3 gD(N_ATOMS / 32, 2);
    k_phaseD<<<gD, 256>>>(K);
    k_reduceD<<<(N_ATOMS * 64) / 256, 256>>>((float*)d_out);
}

// round 4
// speedup vs baseline: 1.3721x; 1.3721x over previous
#include <cuda_runtime.h>
#include <math.h>

#define N_ATOMS 8192
#define D_DIM   128
#define K_MAX   4224
#define SPLIT_A 8
#define TWO_PI  6.28318530717958647692f

typedef unsigned long long u64;

// ---------------- static device scratch ----------------
__device__ float2 g_csf[(size_t)K_MAX * N_ATOMS];   // [K][N] {cos,sin} fwd
__device__ float2 g_csi[(size_t)N_ATOMS * K_MAX];   // [N][K] {cos,sin} inv
__device__ u64   g_pK[SPLIT_A][(size_t)K_MAX * D_DIM];  // {kpr,kpi} partials
__device__ u64   g_pV[SPLIT_A][(size_t)K_MAX * D_DIM];  // {vpr,vpi} partials
__device__ float g_vpr[K_MAX * D_DIM];
__device__ float g_vpi[K_MAX * D_DIM];
__device__ float g_akp[K_MAX * D_DIM];
__device__ float g_qabs[(size_t)N_ATOMS * D_DIM];
__device__ float g_aw[(size_t)N_ATOMS * K_MAX];
__device__ u64   g_pD[2][(size_t)N_ATOMS * 64];

// ---------------- f32x2 helpers ----------------
__device__ __forceinline__ u64 pk2(float lo, float hi) {
    u64 r; asm("mov.b64 %0,{%1,%2};" : "=l"(r) : "f"(lo), "f"(hi)); return r;
}
__device__ __forceinline__ u64 dup2(float x) { return pk2(x, x); }
__device__ __forceinline__ void fma2(u64& d, u64 a, u64 b) {
    asm("fma.rn.f32x2 %0,%1,%2,%0;" : "+l"(d) : "l"(a), "l"(b));
}
__device__ __forceinline__ float2 up2(u64 v) {
    float2 f; asm("mov.b64 {%0,%1},%2;" : "=f"(f.x), "=f"(f.y) : "l"(v)); return f;
}

// ---------------- plane-wave table helper ----------------
__device__ __forceinline__ void build_tables_one(
    float rx, float ry, float rz,
    float* exr, float* exi, float* eyr, float* eyi,
    float* ezr, float* ezi, int pitch)
{
    #pragma unroll
    for (int j = 0; j <= 12; j++) {
        float s, c;
        sincosf(TWO_PI * rx * (float)j, &s, &c);
        exr[j * pitch] = c; exi[j * pitch] = s;
    }
    #pragma unroll
    for (int j = 0; j <= 12; j++) {
        float s, c;
        sincosf(TWO_PI * ry * (float)j, &s, &c);
        eyr[(12 + j) * pitch] = c; eyi[(12 + j) * pitch] = s;
        eyr[(12 - j) * pitch] = c; eyi[(12 - j) * pitch] = -s;
    }
    #pragma unroll
    for (int j = 0; j <= 12; j++) {
        float s, c;
        sincosf(TWO_PI * rz * (float)j, &s, &c);
        ezr[(12 + j) * pitch] = c; ezi[(12 + j) * pitch] = s;
        ezr[(12 - j) * pitch] = c; ezi[(12 - j) * pitch] = -s;
    }
}

// ---------------- kernel 1a: forward E matrix [K][N] ----------------
__global__ void __launch_bounds__(256) k_build_fwd(
    const float* __restrict__ pos, const float* __restrict__ cell,
    const int* __restrict__ kfwd, int K)
{
    __shared__ float exr[13][32], exi[13][32];
    __shared__ float eyr[25][32], eyi[25][32];
    __shared__ float ezr[25][32], ezi[25][32];

    const int tx = threadIdx.x, ty = threadIdx.y;
    const int n0 = blockIdx.x * 32;

    if (ty == 0) {
        int n = n0 + tx;
        float bx = cell[0], by = cell[4], bz = cell[8];
        build_tables_one(pos[n*3+0]/bx, pos[n*3+1]/by, pos[n*3+2]/bz,
                         &exr[0][tx], &exi[0][tx], &eyr[0][tx], &eyi[0][tx],
                         &ezr[0][tx], &ezi[0][tx], 32);
    }
    __syncthreads();

    for (int k = ty; k < K; k += 8) {
        int a = kfwd[3*k+0], b = kfwd[3*k+1] + 12, c = kfwd[3*k+2] + 12;
        float xr = exr[a][tx], xi = exi[a][tx];
        float yr = eyr[b][tx], yi = eyi[b][tx];
        float zr = ezr[c][tx], zi = ezi[c][tx];
        float pr = xr*yr - xi*yi, pi = xr*yi + xi*yr;
        g_csf[(size_t)k * N_ATOMS + n0 + tx] =
            make_float2(pr*zr - pi*zi, pr*zi + pi*zr);
    }
}

// ---------------- kernel 1b: inverse E matrix [N][K] ----------------
__global__ void __launch_bounds__(256) k_build_inv(
    const float* __restrict__ pos, const float* __restrict__ cell,
    const int* __restrict__ kinv, int K)
{
    __shared__ float exr[13][9], exi[13][9];
    __shared__ float eyr[25][9], eyi[25][9];
    __shared__ float ezr[25][9], ezi[25][9];

    const int tx = threadIdx.x, ty = threadIdx.y;
    const int tid = tx + 32 * ty;
    const int n0 = blockIdx.x * 8;

    if (tid < 8) {
        int n = n0 + tid;
        float bx = cell[0], by = cell[4], bz = cell[8];
        build_tables_one(pos[n*3+0]/bx, pos[n*3+1]/by, pos[n*3+2]/bz,
                         &exr[0][tid], &exi[0][tid], &eyr[0][tid], &eyi[0][tid],
                         &ezr[0][tid], &ezi[0][tid], 9);
    }
    __syncthreads();

    for (int k = tx; k < K; k += 32) {
        int a = kinv[3*k+0], b = kinv[3*k+1] + 12, c = kinv[3*k+2] + 12;
        float xr = exr[a][ty], xi = exi[a][ty];
        float yr = eyr[b][ty], yi = eyi[b][ty];
        float zr = ezr[c][ty], zi = ezi[c][ty];
        float pr = xr*yr - xi*yi, pi = xr*yi + xi*yr;
        g_csi[(size_t)(n0 + ty) * K + k] =
            make_float2(pr*zr - pi*zi, pr*zi + pi*zr);
    }
}

// ---------------- kernel 1c: |q| ----------------
__global__ void k_absq(const float* __restrict__ q)
{
    int i = blockIdx.x * 256 + threadIdx.x;
    g_qabs[i] = fabsf(q[i]);
}

// ---------------- kernel 2: phase A split-N GEMM ----------------
// tile 32k x 128d; thread: 4 k-rows (ty + 8j) x 4 d-cols (tx + 32m).
// cos/sin distributed via registers + shfl (lane nn holds atom nn's value);
// only k/v go through the smem crossbar.
__global__ void __launch_bounds__(256, 2) k_phaseA(
    const float* __restrict__ kv, const float* __restrict__ vv, int K)
{
    __shared__ float s_k[32][128];  // [n][d]
    __shared__ float s_v[32][128];

    const int t  = threadIdx.x;
    const int tx = t & 31;
    const int ty = t >> 5;
    const int k0 = blockIdx.x * 32;
    const int nb0 = blockIdx.y * (N_ATOMS / SPLIT_A);
    const int nb_end = nb0 + (N_ATOMS / SPLIT_A);

    u64 aK[4][4], aV[4][4];
    #pragma unroll
    for (int j = 0; j < 4; j++)
        #pragma unroll
        for (int m = 0; m < 4; m++) { aK[j][m] = 0ull; aV[j][m] = 0ull; }

    for (int nb = nb0; nb < nb_end; nb += 32) {
        // per-lane CS for this warp's 4 k-rows at atom nb+tx (no smem)
        u64 csr[4];
        #pragma unroll
        for (int j = 0; j < 4; j++) {
            int kl = ty + 8 * j;
            csr[j] = *(const u64*)&g_csf[(size_t)(k0 + kl) * N_ATOMS + nb + tx];
        }
        __syncthreads();
        #pragma unroll
        for (int j = 0; j < 4; j++) {
            int row = ty + 8 * j;
            *(float4*)&s_k[row][tx*4] = *(const float4*)&kv[(size_t)(nb+row)*128 + tx*4];
            *(float4*)&s_v[row][tx*4] = *(const float4*)&vv[(size_t)(nb+row)*128 + tx*4];
        }
        __syncthreads();

        #pragma unroll
        for (int nn = 0; nn < 32; nn++) {
            u64 CS[4];
            #pragma unroll
            for (int j = 0; j < 4; j++)
                CS[j] = __shfl_sync(0xffffffffu, csr[j], nn);
            #pragma unroll
            for (int m = 0; m < 4; m++) {
                int d = tx + 32 * m;
                u64 Kd = dup2(s_k[nn][d]);
                u64 Vd = dup2(s_v[nn][d]);
                #pragma unroll
                for (int j = 0; j < 4; j++) {
                    fma2(aK[j][m], CS[j], Kd);   // {sum c*k, sum s*k}
                    fma2(aV[j][m], CS[j], Vd);   // {sum c*v, sum s*v}
                }
            }
        }
    }

    const int sp = blockIdx.y;
    #pragma unroll
    for (int j = 0; j < 4; j++) {
        int k = k0 + ty + 8 * j;
        if (k < K) {
            #pragma unroll
            for (int m = 0; m < 4; m++) {
                int d = tx + 32 * m;
                g_pK[sp][(size_t)k * 128 + d] = aK[j][m];
                g_pV[sp][(size_t)k * 128 + d] = aV[j][m];
            }
        }
    }
}

// ---------------- kernel 3: reduce splits + |k_pot| ----------------
__global__ void k_reduceA(int K)
{
    int i = blockIdx.x * 256 + threadIdx.x;
    if (i >= K * 128) return;
    float kr = 0.f, ki = 0.f, vr = 0.f, vi = 0.f;
    #pragma unroll
    for (int s = 0; s < SPLIT_A; s++) {
        float2 a = up2(g_pK[s][i]);
        float2 b = up2(g_pV[s][i]);
        kr += a.x; ki += a.y; vr += b.x; vi += b.y;
    }
    g_vpr[i] = vr; g_vpi[i] = vi;
    g_akp[i] = sqrtf(kr*kr + ki*ki);
}

// ---------------- kernel 4: aw = |q| @ |k_pot|^T (round-2 version) ----------------
__global__ void __launch_bounds__(256) k_phaseB(int K)
{
    __shared__ float s_a[16][132];  // [d][n]
    __shared__ float s_b[16][68];   // [d][k]

    const int t  = threadIdx.x;
    const int tx = t & 15;          // k cols tx*4..+3
    const int ty = t >> 4;          // n rows ty*8..+7
    const int kb = blockIdx.x * 64;
    const int nb = blockIdx.y * 128;

    u64 ac[8][2];
    #pragma unroll
    for (int i = 0; i < 8; i++) { ac[i][0] = 0ull; ac[i][1] = 0ull; }

    for (int d0 = 0; d0 < 128; d0 += 16) {
        __syncthreads();
        #pragma unroll
        for (int i = 0; i < 8; i++) {
            int r = ty + 16 * i;
            s_a[tx][r] = g_qabs[(size_t)(nb + r) * 128 + d0 + tx];
        }
        #pragma unroll
        for (int i = 0; i < 4; i++) {
            int r = ty + 16 * i;
            s_b[tx][r] = (kb + r < K) ? g_akp[(kb + r) * 128 + d0 + tx] : 0.f;
        }
        __syncthreads();
        #pragma unroll
        for (int dd = 0; dd < 16; dd++) {
            ulonglong2 b = *(const ulonglong2*)&s_b[dd][tx * 4];
            float4 a0 = *(const float4*)&s_a[dd][ty * 8];
            float4 a1 = *(const float4*)&s_a[dd][ty * 8 + 4];
            u64 A;
            A = dup2(a0.x); fma2(ac[0][0], A, b.x); fma2(ac[0][1], A, b.y);
            A = dup2(a0.y); fma2(ac[1][0], A, b.x); fma2(ac[1][1], A, b.y);
            A = dup2(a0.z); fma2(ac[2][0], A, b.x); fma2(ac[2][1], A, b.y);
            A = dup2(a0.w); fma2(ac[3][0], A, b.x); fma2(ac[3][1], A, b.y);
            A = dup2(a1.x); fma2(ac[4][0], A, b.x); fma2(ac[4][1], A, b.y);
            A = dup2(a1.y); fma2(ac[5][0], A, b.x); fma2(ac[5][1], A, b.y);
            A = dup2(a1.z); fma2(ac[6][0], A, b.x); fma2(ac[6][1], A, b.y);
            A = dup2(a1.w); fma2(ac[7][0], A, b.x); fma2(ac[7][1], A, b.y);
        }
    }
    #pragma unroll
    for (int i = 0; i < 8; i++) {
        int n = nb + ty * 8 + i;
        size_t base = (size_t)n * K + kb + tx * 4;
        float2 lo = up2(ac[i][0]), hi = up2(ac[i][1]);
        float vals[4] = {lo.x, lo.y, hi.x, hi.y};
        #pragma unroll
        for (int j = 0; j < 4; j++)
            if (kb + tx * 4 + j < K) g_aw[base + j] = vals[j];
    }
}

// ---------------- kernel 5: row softmax in place ----------------
__global__ void __launch_bounds__(256) k_softmax(int K)
{
    __shared__ float buf[K_MAX];
    __shared__ float red[8];
    const int n = blockIdx.x;
    const int t = threadIdx.x;
    float* row = g_aw + (size_t)n * K;

    float mx = -1e30f;
    for (int i = t; i < K; i += 256) { float v = row[i]; buf[i] = v; mx = fmaxf(mx, v); }
    #pragma unroll
    for (int o = 16; o; o >>= 1) mx = fmaxf(mx, __shfl_xor_sync(0xffffffffu, mx, o));
    if ((t & 31) == 0) red[t >> 5] = mx;
    __syncthreads();
    float gmax = red[0];
    #pragma unroll
    for (int j = 1; j < 8; j++) gmax = fmaxf(gmax, red[j]);
    __syncthreads();

    float s = 0.f;
    for (int i = t; i < K; i += 256) { float e = expf(buf[i] - gmax); buf[i] = e; s += e; }
    #pragma unroll
    for (int o = 16; o; o >>= 1) s += __shfl_xor_sync(0xffffffffu, s, o);
    if ((t & 31) == 0) red[t >> 5] = s;
    __syncthreads();
    float gsum = 0.f;
    #pragma unroll
    for (int j = 0; j < 8; j++) gsum += red[j];
    float inv = 1.f / gsum;
    for (int i = t; i < K; i += 256) row[i] = buf[i] * inv;
}

// ---------------- kernel 6: phase D (w via shfl, split-K=2) ----------------
// tile 64n x 128d, k-tile 32; warp: 8 n-rows (ty*8+j), lane: 2 d-pairs
// (d = 2*tx + 64*p). w = sm*eik_i held pre-duplicated in regs, shfl'd by kk.
__global__ void __launch_bounds__(256, 2) k_phaseD(int K)
{
    __shared__ float s_vr[32][128];  // [kk][d]
    __shared__ float s_vi[32][128];

    const int t  = threadIdx.x;
    const int tx = t & 31;           // lane
    const int ty = t >> 5;           // warp -> rows ty*8..ty*8+7
    const int n0 = blockIdx.x * 64;
    const int z  = blockIdx.y;

    const int ksteps = (K + 31) / 32;
    const int half = (ksteps + 1) / 2;
    const int ks_lo = z ? half : 0;
    const int ks_hi = z ? ksteps : half;

    u64 acc[8][2];
    #pragma unroll
    for (int j = 0; j < 8; j++) { acc[j][0] = 0ull; acc[j][1] = 0ull; }

    for (int ks = ks_lo; ks < ks_hi; ks++) {
        const int k0 = ks * 32;
        // per-lane w for this warp's 8 rows at k = k0 + lane (registers)
        u64 wr[8], wi[8];
        {
            const int k = k0 + tx;
            const bool ok = (k < K);
            #pragma unroll
            for (int j = 0; j < 8; j++) {
                float a = 0.f, b = 0.f;
                if (ok) {
                    size_t gi = (size_t)(n0 + ty * 8 + j) * K + k;
                    float sm = g_aw[gi];
                    float2 cs = g_csi[gi];
                    a = sm * cs.x; b = sm * cs.y;
                }
                wr[j] = dup2(a); wi[j] = dup2(b);
            }
        }
        __syncthreads();
        // v fill: 32 kk x 128 d  (each thread 4 float4 per array)
        #pragma unroll
        for (int j = 0; j < 4; j++) {
            int lin = t + 256 * j;
            int kk = lin >> 6, c4 = lin & 63;   // 32 kk x 64 float4-groups? no:
            // 32*128 floats = 1024 float4; lin in [0,1024): kk = lin/32, col = lin%32
            kk = lin >> 5; c4 = lin & 31;
            float4 a = make_float4(0.f, 0.f, 0.f, 0.f);
            float4 b = make_float4(0.f, 0.f, 0.f, 0.f);
            if (k0 + kk < K) {
                a = *(const float4*)&g_vpr[(k0 + kk) * 128 + c4 * 4];
                b = *(const float4*)&g_vpi[(k0 + kk) * 128 + c4 * 4];
            }
            *(float4*)&s_vr[kk][c4 * 4] = a;
            *(float4*)&s_vi[kk][c4 * 4] = b;
        }
        __syncthreads();

        #pragma unroll
        for (int kk = 0; kk < 32; kk++) {
            u64 vr0 = *(const u64*)&s_vr[kk][2 * tx];
            u64 vi0 = *(const u64*)&s_vi[kk][2 * tx];
            u64 vr1 = *(const u64*)&s_vr[kk][2 * tx + 64];
            u64 vi1 = *(const u64*)&s_vi[kk][2 * tx + 64];
            #pragma unroll
            for (int j = 0; j < 8; j++) {
                u64 WR = __shfl_sync(0xffffffffu, wr[j], kk);
                u64 WI = __shfl_sync(0xffffffffu, wi[j], kk);
                fma2(acc[j][0], WR, vr0); fma2(acc[j][0], WI, vi0);
                fma2(acc[j][1], WR, vr1); fma2(acc[j][1], WI, vi1);
            }
        }
    }

    #pragma unroll
    for (int j = 0; j < 8; j++) {
        int row = n0 + ty * 8 + j;
        g_pD[z][(size_t)row * 64 + tx]      = acc[j][0];
        g_pD[z][(size_t)row * 64 + tx + 32] = acc[j][1];
    }
}

// ---------------- kernel 7: phase D reduce ----------------
__global__ void k_reduceD(float* __restrict__ out)
{
    int i = blockIdx.x * 256 + threadIdx.x;
    float2 a = up2(g_pD[0][i]);
    float2 b = up2(g_pD[1][i]);
    ((float2*)out)[i] = make_float2(a.x + b.x, a.y + b.y);
}

// ---------------- launch ----------------
extern "C" void kernel_launch(void* const* d_in, const int* in_sizes, int n_in,
                              void* d_out, int out_size)
{
    const float* q    = (const float*)d_in[0];
    const float* kvec = (const float*)d_in[1];
    const float* vvec = (const float*)d_in[2];
    const float* pos  = (const float*)d_in[3];
    const float* cell = (const float*)d_in[4];
    const int*   kfwd = (const int*)d_in[6];
    const int*   kinv = (const int*)d_in[7];
    const int K = in_sizes[6] / 3;

    dim3 b(32, 8);
    k_build_fwd<<<N_ATOMS / 32, b>>>(pos, cell, kfwd, K);
    k_build_inv<<<N_ATOMS / 8, b>>>(pos, cell, kinv, K);
    k_absq<<<(N_ATOMS * D_DIM) / 256, 256>>>(q);

    dim3 gA((K + 31) / 32, SPLIT_A);
    k_phaseA<<<gA, 256>>>(kvec, vvec, K);
    k_reduceA<<<(K * D_DIM + 255) / 256, 256>>>(K);

    dim3 gB((K + 63) / 64, N_ATOMS / 128);
    k_phaseB<<<gB, 256>>>(K);
    k_softmax<<<N_ATOMS, 256>>>(K);

    dim3 gD(N_ATOMS / 64, 2);
    k_phaseD<<<gD, 256>>>(K);
    k_reduceD<<<(N_ATOMS * 64) / 256, 256>>>((float*)d_out);
}